// round 2
// baseline (speedup 1.0000x reference)
#include <cuda_runtime.h>

#define NN   100000
#define EE   3200000
#define FDIM 128
#define HD   20
#define CD   10
#define EPSV 1e-5f

// ---------------- scratch (device globals; no allocation allowed) ----------------
__device__ float g_deg[NN];
__device__ float g_dinv[NN];
__device__ int   g_count[NN];
__device__ int   g_off[NN + 1];
__device__ int   g_cursor[NN];
__device__ int2  g_csr[EE];          // .x = src node, .y = coef bits (float)
__device__ float g_h[(size_t)NN * HD];
__device__ float g_o1[(size_t)NN * HD];
__device__ float g_o2[(size_t)NN * HD];
__device__ float g_o3[(size_t)NN * HD];
__device__ float g_stats[4 * HD];    // [0..19]=sum1 [20..39]=sq1 [40..59]=sum2 [60..79]=sq2

// ---------------- init ----------------
__global__ void k_init(int n) {
    int i = blockIdx.x * blockDim.x + threadIdx.x;
    if (i < n) { g_deg[i] = 1.0f; g_count[i] = 0; }  // self-loop weight = 1
    if (i < 4 * HD) g_stats[i] = 0.0f;
}

// ---------------- weighted degree + CSR histogram ----------------
__global__ void k_hist(const int* __restrict__ dst, const float* __restrict__ ew, int e) {
    int i = blockIdx.x * blockDim.x + threadIdx.x;
    if (i >= e) return;
    int d = dst[i];
    atomicAdd(&g_deg[d], ew[i]);
    atomicAdd(&g_count[d], 1);
}

__global__ void k_dinv(int n) {
    int i = blockIdx.x * blockDim.x + threadIdx.x;
    if (i >= n) return;
    float d = g_deg[i];
    g_dinv[i] = (d > 0.0f) ? rsqrtf(d) : 0.0f;
}

// ---------------- single-block exclusive scan of counts -> offsets ----------------
__global__ void k_scan(int n) {
    __shared__ int s[1024];
    int t = threadIdx.x;
    int chunk = (n + 1023) >> 10;
    int st = t * chunk;
    int en = min(st + chunk, n);
    int loc = 0;
    for (int i = st; i < en; i++) loc += g_count[i];
    s[t] = loc;
    __syncthreads();
    for (int off = 1; off < 1024; off <<= 1) {
        int v = (t >= off) ? s[t - off] : 0;
        __syncthreads();
        s[t] += v;
        __syncthreads();
    }
    int run = s[t] - loc;  // exclusive prefix
    for (int i = st; i < en; i++) {
        g_off[i] = run;
        g_cursor[i] = run;
        run += g_count[i];
    }
    if (t == 1023) g_off[n] = s[1023];
}

// ---------------- CSR fill (coef baked in; reused by all 3 convs) ----------------
__global__ void k_fill(const int* __restrict__ src, const int* __restrict__ dst,
                       const float* __restrict__ ew, int e) {
    int i = blockIdx.x * blockDim.x + threadIdx.x;
    if (i >= e) return;
    int sN = src[i];
    int d  = dst[i];
    int pos = atomicAdd(&g_cursor[d], 1);
    float c = g_dinv[sN] * ew[i] * g_dinv[d];
    g_csr[pos] = make_int2(sN, __float_as_int(c));
}

// ---------------- GEMM1: g_h = x @ W1  (K=128) ----------------
__global__ void k_gemm1(const float* __restrict__ x, const float* __restrict__ W, int n) {
    __shared__ float sw[HD * FDIM];  // transposed: sw[j*F + k]
    for (int idx = threadIdx.x; idx < FDIM * HD; idx += blockDim.x) {
        int k = idx / HD, j = idx % HD;
        sw[j * FDIM + k] = W[idx];
    }
    __syncthreads();
    int i = blockIdx.x * blockDim.x + threadIdx.x;
    if (i >= n) return;
    const float4* xr  = reinterpret_cast<const float4*>(x + (size_t)i * FDIM);
    const float4* sw4 = reinterpret_cast<const float4*>(sw);
    float acc[HD];
#pragma unroll
    for (int j = 0; j < HD; j++) acc[j] = 0.0f;
#pragma unroll 4
    for (int k4 = 0; k4 < FDIM / 4; k4++) {
        float4 v = xr[k4];
#pragma unroll
        for (int j = 0; j < HD; j++) {
            float4 w = sw4[j * (FDIM / 4) + k4];
            acc[j] += v.x * w.x + v.y * w.y + v.z * w.z + v.w * w.w;
        }
    }
    float* hr = g_h + (size_t)i * HD;
#pragma unroll
    for (int j = 0; j < HD; j++) hr[j] = acc[j];
}

// ---------------- small GEMM: g_h = o{1|2} @ W  (K=20) ----------------
__global__ void k_gemm_small(const float* __restrict__ W, int which_in, int n) {
    __shared__ float sw[HD * HD];  // transposed: sw[j*HD + k]
    for (int idx = threadIdx.x; idx < HD * HD; idx += blockDim.x) {
        int k = idx / HD, j = idx % HD;
        sw[j * HD + k] = W[idx];
    }
    __syncthreads();
    int i = blockIdx.x * blockDim.x + threadIdx.x;
    if (i >= n) return;
    const float* in = (which_in == 0) ? g_o1 : g_o2;
    const float4* xr = reinterpret_cast<const float4*>(in + (size_t)i * HD);
    float4 v[5];
#pragma unroll
    for (int q = 0; q < 5; q++) v[q] = xr[q];
    const float4* sw4 = reinterpret_cast<const float4*>(sw);
    float* hr = g_h + (size_t)i * HD;
#pragma unroll
    for (int j = 0; j < HD; j++) {
        float acc = 0.0f;
#pragma unroll
        for (int q = 0; q < 5; q++) {
            float4 w = sw4[j * 5 + q];
            acc += v[q].x * w.x + v[q].y * w.y + v[q].z * w.z + v[q].w * w.w;
        }
        hr[j] = acc;
    }
}

// ---------------- pull aggregation: warp per node, no atomics ----------------
// o[dst,j] = relu( b[j] + dinv[dst]^2 * h[dst,j] + sum_e coef[e] * h[src[e],j] )
__global__ void k_pull(const float* __restrict__ bias, int which, int n) {
    int gw   = (blockIdx.x * blockDim.x + threadIdx.x) >> 5;
    int lane = threadIdx.x & 31;
    if (gw >= n) return;
    int s = g_off[gw];
    int e = g_off[gw + 1];
    int col = (lane < HD) ? lane : 0;
    float acc = 0.0f, bj = 0.0f;
    if (lane < HD) {
        float di = g_dinv[gw];
        acc = g_h[(size_t)gw * HD + lane] * di * di;
        bj  = bias[lane];
    }
    int k = s;
    for (; k + 3 < e; k += 4) {
        int2 p0 = g_csr[k];
        int2 p1 = g_csr[k + 1];
        int2 p2 = g_csr[k + 2];
        int2 p3 = g_csr[k + 3];
        float h0 = g_h[(size_t)p0.x * HD + col];
        float h1 = g_h[(size_t)p1.x * HD + col];
        float h2 = g_h[(size_t)p2.x * HD + col];
        float h3 = g_h[(size_t)p3.x * HD + col];
        if (lane < HD) {
            acc += __int_as_float(p0.y) * h0;
            acc += __int_as_float(p1.y) * h1;
            acc += __int_as_float(p2.y) * h2;
            acc += __int_as_float(p3.y) * h3;
        }
    }
    for (; k < e; k++) {
        int2 p = g_csr[k];
        float hv = g_h[(size_t)p.x * HD + col];
        if (lane < HD) acc += __int_as_float(p.y) * hv;
    }
    if (lane < HD) {
        float v = acc + bj;
        float* o = (which == 0) ? g_o1 : (which == 1) ? g_o2 : g_o3;
        o[(size_t)gw * HD + lane] = (v > 0.0f) ? v : 0.0f;
    }
}

// ---------------- BN statistics (sum, sumsq per feature) ----------------
__global__ void k_stats(int which, int base, int n) {
    int lane = threadIdx.x & 31;
    if (lane >= HD) return;
    int gw = (blockIdx.x * blockDim.x + threadIdx.x) >> 5;
    int nw = (gridDim.x * blockDim.x) >> 5;
    const float* o = (which == 0) ? g_o1 : g_o2;
    float s = 0.0f, ss = 0.0f;
    for (int r = gw; r < n; r += nw) {
        float v = o[(size_t)r * HD + lane];
        s += v;
        ss += v * v;
    }
    atomicAdd(&g_stats[base + lane], s);
    atomicAdd(&g_stats[base + HD + lane], ss);
}

// ---------------- BN apply (in place) ----------------
__global__ void k_bn(int which, int base, const float* __restrict__ gam,
                     const float* __restrict__ bet, int n) {
    int idx = blockIdx.x * blockDim.x + threadIdx.x;
    int tot = n * HD;
    if (idx >= tot) return;
    int j = idx % HD;
    float inv = 1.0f / (float)n;
    float m   = g_stats[base + j] * inv;
    float var = g_stats[base + HD + j] * inv - m * m;
    float r   = rsqrtf(var + EPSV);
    float* o = (which == 0) ? g_o1 : g_o2;
    o[idx] = (o[idx] - m) * r * gam[j] + bet[j];
}

// ---------------- head: out = concat(o1,o2,o3) @ Wl + bl ----------------
__global__ void k_final(const float* __restrict__ Wl, const float* __restrict__ bl,
                        float* __restrict__ out, int n) {
    __shared__ float sw[CD * 3 * HD];  // transposed: sw[c*60 + j]
    __shared__ float sb[CD];
    for (int idx = threadIdx.x; idx < 3 * HD * CD; idx += blockDim.x) {
        int j = idx / CD, c = idx % CD;
        sw[c * 3 * HD + j] = Wl[idx];
    }
    if (threadIdx.x < CD) sb[threadIdx.x] = bl[threadIdx.x];
    __syncthreads();
    int i = blockIdx.x * blockDim.x + threadIdx.x;
    if (i >= n) return;
    float4 ev[15];
    const float4* a  = reinterpret_cast<const float4*>(g_o1 + (size_t)i * HD);
    const float4* b  = reinterpret_cast<const float4*>(g_o2 + (size_t)i * HD);
    const float4* c4 = reinterpret_cast<const float4*>(g_o3 + (size_t)i * HD);
#pragma unroll
    for (int q = 0; q < 5; q++) { ev[q] = a[q]; ev[5 + q] = b[q]; ev[10 + q] = c4[q]; }
#pragma unroll
    for (int cc = 0; cc < CD; cc++) {
        float acc = sb[cc];
        const float4* w4 = reinterpret_cast<const float4*>(sw + cc * 3 * HD);
#pragma unroll
        for (int q = 0; q < 15; q++) {
            float4 w = w4[q];
            float4 e = ev[q];
            acc += e.x * w.x + e.y * w.y + e.z * w.z + e.w * w.w;
        }
        out[(size_t)i * CD + cc] = acc;
    }
}

// ---------------- launch ----------------
extern "C" void kernel_launch(void* const* d_in, const int* in_sizes, int n_in,
                              void* d_out, int out_size) {
    const float* x   = (const float*)d_in[0];
    const int*   ei  = (const int*)d_in[1];
    const float* ew  = (const float*)d_in[2];
    const float* W1  = (const float*)d_in[3];
    const float* b1  = (const float*)d_in[4];
    const float* g1  = (const float*)d_in[5];
    const float* be1 = (const float*)d_in[6];
    const float* W2  = (const float*)d_in[7];
    const float* b2  = (const float*)d_in[8];
    const float* g2  = (const float*)d_in[9];
    const float* be2 = (const float*)d_in[10];
    const float* W3  = (const float*)d_in[11];
    const float* b3  = (const float*)d_in[12];
    const float* Wl  = (const float*)d_in[13];
    const float* bl  = (const float*)d_in[14];

    int n = in_sizes[0] / FDIM;   // 100000
    int e = in_sizes[2];          // 3200000
    const int* src = ei;
    const int* dst = ei + e;

    int nb_n  = (n + 255) / 256;
    int nb_e  = (e + 255) / 256;
    int nb_p  = (n * 32 + 255) / 256;   // warp per node
    int nb_bn = (n * HD + 255) / 256;

    // graph preprocessing (shared by all 3 convs)
    k_init<<<nb_n, 256>>>(n);
    k_hist<<<nb_e, 256>>>(dst, ew, e);
    k_dinv<<<nb_n, 256>>>(n);
    k_scan<<<1, 1024>>>(n);
    k_fill<<<nb_e, 256>>>(src, dst, ew, e);

    // conv1 + BN
    k_gemm1<<<nb_n, 256>>>(x, W1, n);
    k_pull<<<nb_p, 256>>>(b1, 0, n);
    k_stats<<<148, 256>>>(0, 0, n);
    k_bn<<<nb_bn, 256>>>(0, 0, g1, be1, n);

    // conv2 + BN
    k_gemm_small<<<nb_n, 256>>>(W2, 0, n);
    k_pull<<<nb_p, 256>>>(b2, 1, n);
    k_stats<<<148, 256>>>(1, 40, n);
    k_bn<<<nb_bn, 256>>>(1, 40, g2, be2, n);

    // conv3 (relu only)
    k_gemm_small<<<nb_n, 256>>>(W3, 1, n);
    k_pull<<<nb_p, 256>>>(b3, 2, n);

    // classifier head
    k_final<<<nb_n, 256>>>(Wl, bl, (float*)d_out, n);
}

// round 3
// speedup vs baseline: 1.4108x; 1.4108x over previous
#include <cuda_runtime.h>

#define NN   100000
#define EE   3200000
#define FDIM 128
#define HD   20
#define CD   10
#define EPSV 1e-5f

#define SCAN_CHUNK 256
#define NBLK_SCAN  ((NN + SCAN_CHUNK - 1) / SCAN_CHUNK)   // 391

// ---------------- scratch (device globals; no allocation allowed) ----------------
__device__ float g_deg[NN];
__device__ float g_dinv[NN];
__device__ int   g_count[NN];
__device__ int   g_off[NN + 1];
__device__ int   g_cursor[NN];
__device__ int   g_bsum[NBLK_SCAN + 1];
__device__ int2  g_csr[EE];          // .x = src node, .y = coef bits (float)
__device__ float g_h[(size_t)NN * HD];
__device__ float g_o1[(size_t)NN * HD];
__device__ float g_o2[(size_t)NN * HD];
__device__ float g_o3[(size_t)NN * HD];
__device__ float g_stats[4 * HD];    // [0..19]=sum1 [20..39]=sq1 [40..59]=sum2 [60..79]=sq2

// ---------------- init ----------------
__global__ void k_init(int n) {
    int i = blockIdx.x * blockDim.x + threadIdx.x;
    if (i < n) { g_deg[i] = 1.0f; g_count[i] = 0; }  // self-loop weight = 1
    if (i < 4 * HD) g_stats[i] = 0.0f;
}

// ---------------- weighted degree + CSR histogram ----------------
__global__ void k_hist(const int* __restrict__ dst, const float* __restrict__ ew, int e) {
    int i = blockIdx.x * blockDim.x + threadIdx.x;
    if (i >= e) return;
    int d = dst[i];
    atomicAdd(&g_deg[d], ew[i]);
    atomicAdd(&g_count[d], 1);
}

__global__ void k_dinv(int n) {
    int i = blockIdx.x * blockDim.x + threadIdx.x;
    if (i >= n) return;
    float d = g_deg[i];
    g_dinv[i] = (d > 0.0f) ? rsqrtf(d) : 0.0f;
}

// ---------------- multi-block exclusive scan: phase 1 (per-block reduce) ----------
__global__ void k_scan1(int n) {
    __shared__ int s[SCAN_CHUNK];
    int t = threadIdx.x;
    int i = blockIdx.x * SCAN_CHUNK + t;
    int v = (i < n) ? g_count[i] : 0;
    s[t] = v;
    __syncthreads();
#pragma unroll
    for (int off = SCAN_CHUNK / 2; off > 0; off >>= 1) {
        if (t < off) s[t] += s[t + off];
        __syncthreads();
    }
    if (t == 0) g_bsum[blockIdx.x] = s[0];
}

// ---------------- phase 2: single small block scans the block sums --------------
__global__ void k_scan2(int nblk, int n, int e) {
    __shared__ int s[512];
    int t = threadIdx.x;
    int v = (t < nblk) ? g_bsum[t] : 0;
    s[t] = v;
    __syncthreads();
#pragma unroll
    for (int off = 1; off < 512; off <<= 1) {
        int u = (t >= off) ? s[t - off] : 0;
        __syncthreads();
        s[t] += u;
        __syncthreads();
    }
    if (t < nblk) g_bsum[t] = s[t] - v;   // exclusive prefix of block sums
    if (t == 0) g_off[n] = e;             // total count == number of edges
}

// ---------------- phase 3: per-block exclusive scan + block offset ---------------
__global__ void k_scan3(int n) {
    __shared__ int s[SCAN_CHUNK];
    int t = threadIdx.x;
    int i = blockIdx.x * SCAN_CHUNK + t;
    int v = (i < n) ? g_count[i] : 0;
    s[t] = v;
    __syncthreads();
#pragma unroll
    for (int off = 1; off < SCAN_CHUNK; off <<= 1) {
        int u = (t >= off) ? s[t - off] : 0;
        __syncthreads();
        s[t] += u;
        __syncthreads();
    }
    if (i < n) {
        int pos = g_bsum[blockIdx.x] + s[t] - v;  // global exclusive prefix
        g_off[i] = pos;
        g_cursor[i] = pos;
    }
}

// ---------------- CSR fill (coef baked in; reused by all 3 convs) ----------------
__global__ void k_fill(const int* __restrict__ src, const int* __restrict__ dst,
                       const float* __restrict__ ew, int e) {
    int i = blockIdx.x * blockDim.x + threadIdx.x;
    if (i >= e) return;
    int sN = src[i];
    int d  = dst[i];
    int pos = atomicAdd(&g_cursor[d], 1);
    float c = g_dinv[sN] * ew[i] * g_dinv[d];
    g_csr[pos] = make_int2(sN, __float_as_int(c));
}

// ---------------- GEMM1: g_h = x @ W1  (K=128) ----------------
__global__ void k_gemm1(const float* __restrict__ x, const float* __restrict__ W, int n) {
    __shared__ float sw[HD * FDIM];  // transposed: sw[j*F + k]
    for (int idx = threadIdx.x; idx < FDIM * HD; idx += blockDim.x) {
        int k = idx / HD, j = idx % HD;
        sw[j * FDIM + k] = W[idx];
    }
    __syncthreads();
    int i = blockIdx.x * blockDim.x + threadIdx.x;
    if (i >= n) return;
    const float4* xr  = reinterpret_cast<const float4*>(x + (size_t)i * FDIM);
    const float4* sw4 = reinterpret_cast<const float4*>(sw);
    float acc[HD];
#pragma unroll
    for (int j = 0; j < HD; j++) acc[j] = 0.0f;
#pragma unroll 4
    for (int k4 = 0; k4 < FDIM / 4; k4++) {
        float4 v = xr[k4];
#pragma unroll
        for (int j = 0; j < HD; j++) {
            float4 w = sw4[j * (FDIM / 4) + k4];
            acc[j] += v.x * w.x + v.y * w.y + v.z * w.z + v.w * w.w;
        }
    }
    float* hr = g_h + (size_t)i * HD;
#pragma unroll
    for (int j = 0; j < HD; j++) hr[j] = acc[j];
}

// ---------------- small GEMM: g_h = o{1|2} @ W  (K=20) ----------------
__global__ void k_gemm_small(const float* __restrict__ W, int which_in, int n) {
    __shared__ float sw[HD * HD];  // transposed: sw[j*HD + k]
    for (int idx = threadIdx.x; idx < HD * HD; idx += blockDim.x) {
        int k = idx / HD, j = idx % HD;
        sw[j * HD + k] = W[idx];
    }
    __syncthreads();
    int i = blockIdx.x * blockDim.x + threadIdx.x;
    if (i >= n) return;
    const float* in = (which_in == 0) ? g_o1 : g_o2;
    const float4* xr = reinterpret_cast<const float4*>(in + (size_t)i * HD);
    float4 v[5];
#pragma unroll
    for (int q = 0; q < 5; q++) v[q] = xr[q];
    const float4* sw4 = reinterpret_cast<const float4*>(sw);
    float* hr = g_h + (size_t)i * HD;
#pragma unroll
    for (int j = 0; j < HD; j++) {
        float acc = 0.0f;
#pragma unroll
        for (int q = 0; q < 5; q++) {
            float4 w = sw4[j * 5 + q];
            acc += v[q].x * w.x + v[q].y * w.y + v[q].z * w.z + v[q].w * w.w;
        }
        hr[j] = acc;
    }
}

// ---------------- pull aggregation: warp per node, no atomics ----------------
// o[dst,j] = relu( b[j] + dinv[dst]^2 * h[dst,j] + sum_e coef[e] * h[src[e],j] )
__global__ void k_pull(const float* __restrict__ bias, int which, int n) {
    int gw   = (blockIdx.x * blockDim.x + threadIdx.x) >> 5;
    int lane = threadIdx.x & 31;
    if (gw >= n) return;
    int s = g_off[gw];
    int e = g_off[gw + 1];
    int col = (lane < HD) ? lane : 0;
    float acc = 0.0f, bj = 0.0f;
    if (lane < HD) {
        float di = g_dinv[gw];
        acc = g_h[(size_t)gw * HD + lane] * di * di;
        bj  = bias[lane];
    }
    int k = s;
    for (; k + 3 < e; k += 4) {
        int2 p0 = g_csr[k];
        int2 p1 = g_csr[k + 1];
        int2 p2 = g_csr[k + 2];
        int2 p3 = g_csr[k + 3];
        float h0 = g_h[(size_t)p0.x * HD + col];
        float h1 = g_h[(size_t)p1.x * HD + col];
        float h2 = g_h[(size_t)p2.x * HD + col];
        float h3 = g_h[(size_t)p3.x * HD + col];
        if (lane < HD) {
            acc += __int_as_float(p0.y) * h0;
            acc += __int_as_float(p1.y) * h1;
            acc += __int_as_float(p2.y) * h2;
            acc += __int_as_float(p3.y) * h3;
        }
    }
    for (; k < e; k++) {
        int2 p = g_csr[k];
        float hv = g_h[(size_t)p.x * HD + col];
        if (lane < HD) acc += __int_as_float(p.y) * hv;
    }
    if (lane < HD) {
        float v = acc + bj;
        float* o = (which == 0) ? g_o1 : (which == 1) ? g_o2 : g_o3;
        o[(size_t)gw * HD + lane] = (v > 0.0f) ? v : 0.0f;
    }
}

// ---------------- BN statistics (sum, sumsq per feature) ----------------
__global__ void k_stats(int which, int base, int n) {
    int lane = threadIdx.x & 31;
    if (lane >= HD) return;
    int gw = (blockIdx.x * blockDim.x + threadIdx.x) >> 5;
    int nw = (gridDim.x * blockDim.x) >> 5;
    const float* o = (which == 0) ? g_o1 : g_o2;
    float s = 0.0f, ss = 0.0f;
    for (int r = gw; r < n; r += nw) {
        float v = o[(size_t)r * HD + lane];
        s += v;
        ss += v * v;
    }
    atomicAdd(&g_stats[base + lane], s);
    atomicAdd(&g_stats[base + HD + lane], ss);
}

// ---------------- BN apply (in place) ----------------
__global__ void k_bn(int which, int base, const float* __restrict__ gam,
                     const float* __restrict__ bet, int n) {
    int idx = blockIdx.x * blockDim.x + threadIdx.x;
    int tot = n * HD;
    if (idx >= tot) return;
    int j = idx % HD;
    float inv = 1.0f / (float)n;
    float m   = g_stats[base + j] * inv;
    float var = g_stats[base + HD + j] * inv - m * m;
    float r   = rsqrtf(var + EPSV);
    float* o = (which == 0) ? g_o1 : g_o2;
    o[idx] = (o[idx] - m) * r * gam[j] + bet[j];
}

// ---------------- head: out = concat(o1,o2,o3) @ Wl + bl ----------------
__global__ void k_final(const float* __restrict__ Wl, const float* __restrict__ bl,
                        float* __restrict__ out, int n) {
    __shared__ float sw[CD * 3 * HD];  // transposed: sw[c*60 + j]
    __shared__ float sb[CD];
    for (int idx = threadIdx.x; idx < 3 * HD * CD; idx += blockDim.x) {
        int j = idx / CD, c = idx % CD;
        sw[c * 3 * HD + j] = Wl[idx];
    }
    if (threadIdx.x < CD) sb[threadIdx.x] = bl[threadIdx.x];
    __syncthreads();
    int i = blockIdx.x * blockDim.x + threadIdx.x;
    if (i >= n) return;
    float4 ev[15];
    const float4* a  = reinterpret_cast<const float4*>(g_o1 + (size_t)i * HD);
    const float4* b  = reinterpret_cast<const float4*>(g_o2 + (size_t)i * HD);
    const float4* c4 = reinterpret_cast<const float4*>(g_o3 + (size_t)i * HD);
#pragma unroll
    for (int q = 0; q < 5; q++) { ev[q] = a[q]; ev[5 + q] = b[q]; ev[10 + q] = c4[q]; }
#pragma unroll
    for (int cc = 0; cc < CD; cc++) {
        float acc = sb[cc];
        const float4* w4 = reinterpret_cast<const float4*>(sw + cc * 3 * HD);
#pragma unroll
        for (int q = 0; q < 15; q++) {
            float4 w = w4[q];
            float4 e = ev[q];
            acc += e.x * w.x + e.y * w.y + e.z * w.z + e.w * w.w;
        }
        out[(size_t)i * CD + cc] = acc;
    }
}

// ---------------- launch ----------------
extern "C" void kernel_launch(void* const* d_in, const int* in_sizes, int n_in,
                              void* d_out, int out_size) {
    const float* x   = (const float*)d_in[0];
    const int*   ei  = (const int*)d_in[1];
    const float* ew  = (const float*)d_in[2];
    const float* W1  = (const float*)d_in[3];
    const float* b1  = (const float*)d_in[4];
    const float* g1  = (const float*)d_in[5];
    const float* be1 = (const float*)d_in[6];
    const float* W2  = (const float*)d_in[7];
    const float* b2  = (const float*)d_in[8];
    const float* g2  = (const float*)d_in[9];
    const float* be2 = (const float*)d_in[10];
    const float* W3  = (const float*)d_in[11];
    const float* b3  = (const float*)d_in[12];
    const float* Wl  = (const float*)d_in[13];
    const float* bl  = (const float*)d_in[14];

    int n = in_sizes[0] / FDIM;   // 100000
    int e = in_sizes[2];          // 3200000
    const int* src = ei;
    const int* dst = ei + e;

    int nb_n  = (n + 255) / 256;
    int nb_e  = (e + 255) / 256;
    int nb_p  = (n * 32 + 255) / 256;   // warp per node
    int nb_bn = (n * HD + 255) / 256;
    int nb_s  = (n + SCAN_CHUNK - 1) / SCAN_CHUNK;

    // graph preprocessing (shared by all 3 convs)
    k_init<<<nb_n, 256>>>(n);
    k_hist<<<nb_e, 256>>>(dst, ew, e);
    k_dinv<<<nb_n, 256>>>(n);
    k_scan1<<<nb_s, SCAN_CHUNK>>>(n);
    k_scan2<<<1, 512>>>(nb_s, n, e);
    k_scan3<<<nb_s, SCAN_CHUNK>>>(n);
    k_fill<<<nb_e, 256>>>(src, dst, ew, e);

    // conv1 + BN
    k_gemm1<<<nb_n, 256>>>(x, W1, n);
    k_pull<<<nb_p, 256>>>(b1, 0, n);
    k_stats<<<148, 256>>>(0, 0, n);
    k_bn<<<nb_bn, 256>>>(0, 0, g1, be1, n);

    // conv2 + BN
    k_gemm_small<<<nb_n, 256>>>(W2, 0, n);
    k_pull<<<nb_p, 256>>>(b2, 1, n);
    k_stats<<<148, 256>>>(1, 40, n);
    k_bn<<<nb_bn, 256>>>(1, 40, g2, be2, n);

    // conv3 (relu only)
    k_gemm_small<<<nb_n, 256>>>(W3, 1, n);
    k_pull<<<nb_p, 256>>>(b3, 2, n);

    // classifier head
    k_final<<<nb_n, 256>>>(Wl, bl, (float*)d_out, n);
}